// round 12
// baseline (speedup 1.0000x reference)
#include <cuda_runtime.h>

#define J     24
#define TPB   128
#define EPB   64            // elements per block (2 threads per element)
#define PITCH 17            // staging pitch in elems (odd -> conflict-free)
#define WSLAB (75 * PITCH)  // floats per warp slab (75 cols x 16 elems)

__global__ __launch_bounds__(TPB, 9) void fk_kernel(
    const float* __restrict__ angles,   // [B, 24]
    const float* __restrict__ Torg,     // [24, 4, 4]
    const float* __restrict__ axes,     // [24, 3] unit axes
    float* __restrict__ out,            // [B, 75]
    int B)
{
    // Per-joint derived constants: {wx,wy,wz,_, bx,by,bz,_}
    __shared__ __align__(16) float kjc[J][8];
    // Warp-private staging: col-major, addr = col*PITCH + elemInWarp.
    __shared__ float sbuf[(TPB / 32) * WSLAB];   // 20.4 KB

    const int tid  = threadIdx.x;
    const int warp = tid >> 5;
    const int lane = tid & 31;

    // ---- Warp 0: shuffle-scan of cumulative fixed rotations ----
    if (warp == 0) {
        float m[9];
        float ax = 0.f, ay = 0.f, az = 0.f;
        float ux = 0.f, uy = 0.f, uz = 0.f;
        m[0]=1.f; m[1]=0.f; m[2]=0.f;
        m[3]=0.f; m[4]=1.f; m[5]=0.f;
        m[6]=0.f; m[7]=0.f; m[8]=1.f;
        if (lane < J) {
            const float* t = Torg + lane * 16;
            m[0]=t[0]; m[1]=t[1]; m[2]=t[2];   ax=t[3];
            m[3]=t[4]; m[4]=t[5]; m[5]=t[6];   ay=t[7];
            m[6]=t[8]; m[7]=t[9]; m[8]=t[10];  az=t[11];
            ux = axes[lane*3+0]; uy = axes[lane*3+1]; uz = axes[lane*3+2];
        }
        #pragma unroll
        for (int d = 1; d < J; d <<= 1) {          // inclusive Kogge-Stone
            float L[9];
            #pragma unroll
            for (int k = 0; k < 9; ++k)
                L[k] = __shfl_up_sync(0xffffffffu, m[k], d);
            if (lane >= d) {
                float n[9];
                #pragma unroll
                for (int r = 0; r < 3; ++r)
                    #pragma unroll
                    for (int c = 0; c < 3; ++c)
                        n[r*3+c] = L[r*3+0]*m[0*3+c] + L[r*3+1]*m[1*3+c]
                                 + L[r*3+2]*m[2*3+c];
                #pragma unroll
                for (int k = 0; k < 9; ++k) m[k] = n[k];
            }
        }
        float E[9];                                 // exclusive prefix
        #pragma unroll
        for (int k = 0; k < 9; ++k)
            E[k] = __shfl_up_sync(0xffffffffu, m[k], 1);
        if (lane == 0) {
            E[0]=1.f; E[1]=0.f; E[2]=0.f;
            E[3]=0.f; E[4]=1.f; E[5]=0.f;
            E[6]=0.f; E[7]=0.f; E[8]=1.f;
        }
        if (lane < J) {
            kjc[lane][0] = m[0]*ux + m[1]*uy + m[2]*uz;   // w = C_j u
            kjc[lane][1] = m[3]*ux + m[4]*uy + m[5]*uz;
            kjc[lane][2] = m[6]*ux + m[7]*uy + m[8]*uz;
            kjc[lane][3] = 0.f;
            kjc[lane][4] = E[0]*ax + E[1]*ay + E[2]*az;   // b = C_{j-1} t
            kjc[lane][5] = E[3]*ax + E[4]*ay + E[5]*az;
            kjc[lane][6] = E[6]*ax + E[7]*ay + E[8]*az;
            kjc[lane][7] = 0.f;
        }
    }

    const int half = tid & 1;           // 0: joints 0..11, 1: joints 12..23
    const int eW   = lane >> 1;         // element within warp (0..15)
    const int e    = blockIdx.x * EPB + (tid >> 1);
    const bool active = (e < B);
    const int nvalid = min(EPB, B - blockIdx.x * EPB);
    const bool full = (nvalid == EPB);
    float* gout = out + (size_t)blockIdx.x * EPB * 75;

    // This half's 12 angles: 3 LDG.128 (offset e*96 + half*48, 16B aligned).
    float a[12];
    if (active) {
        const float4* ap =
            reinterpret_cast<const float4*>(angles + (size_t)e * J + half * 12);
        #pragma unroll
        for (int q = 0; q < 3; ++q) {
            float4 v = __ldg(ap + q);
            a[4*q+0] = v.x; a[4*q+1] = v.y; a[4*q+2] = v.z; a[4*q+3] = v.w;
        }
    }

    __syncthreads();   // kjc ready

    float* swarp = sbuf + warp * WSLAB;
    const float4* kc = reinterpret_cast<const float4*>(kjc);
    const int jbase = half * 12;

    // State: quaternion P and position p (relative chain for half==1).
    float Pw = 1.f, Px = 0.f, Py = 0.f, Pz = 0.f;
    float px = 0.f, py = 0.f, pz = 0.f;

    if (active) {
        if (half == 0) {   // base_pos cols 0..2
            swarp[0*PITCH + eW] = 0.f;
            swarp[1*PITCH + eW] = 0.f;
            swarp[2*PITCH + eW] = 0.f;
        }
        // Staging base for this half's first position column (3 + 3*jbase).
        float* so = swarp + (3 + 3*jbase) * PITCH + eW;

        #pragma unroll
        for (int k = 0; k < 12; ++k) {
            const int j2 = 2 * (jbase + k);        // runtime base + imm
            const float4 wv = kc[j2];
            const float4 bv = kc[j2 + 1];

            // p += rot(P, b)
            const float tx = Py*bv.z - Pz*bv.y;
            const float ty = Pz*bv.x - Px*bv.z;
            const float tz = Px*bv.y - Py*bv.x;
            const float w2 = Pw + Pw;
            const float ox = Py*tz - Pz*ty;
            const float oy = Pz*tx - Px*tz;
            const float oz = Px*ty - Py*tx;
            px += bv.x + w2*tx + 2.f*ox;
            py += bv.y + w2*ty + 2.f*oy;
            pz += bv.z + w2*tz + 2.f*oz;

            so[(3*k + 0) * PITCH] = px;
            so[(3*k + 1) * PITCH] = py;
            so[(3*k + 2) * PITCH] = pz;

            // Quat update; A needs all 12 (P_11 for fixup), B skips last.
            if (k < 11 || half == 0) {
                float s_, c_;
                __sincosf(0.5f * a[k], &s_, &c_);
                const float qx = s_*wv.x, qy = s_*wv.y, qz = s_*wv.z;
                const float nw = Pw*c_ - Px*qx - Py*qy - Pz*qz;
                const float nx = Pw*qx + Px*c_ + Py*qz - Pz*qy;
                const float ny = Pw*qy - Px*qz + Py*c_ + Pz*qx;
                const float nz = Pw*qz + Px*qy - Py*qx + Pz*c_;
                Pw = nw; Px = nx; Py = ny; Pz = nz;
            }
        }
    }

    __syncwarp();   // both halves staged

    // ---- Fixup: p_j = p11 + R(P11) * p'_j for joints 12..23 ----
    // Pair lanes share A's (P11, p11); each thread fixes 6 joints.
    {
        const int src = lane & ~1;   // A lane of the pair
        const float qw = __shfl_sync(0xffffffffu, Pw, src);
        const float qx = __shfl_sync(0xffffffffu, Px, src);
        const float qy = __shfl_sync(0xffffffffu, Py, src);
        const float qz = __shfl_sync(0xffffffffu, Pz, src);
        const float bx = __shfl_sync(0xffffffffu, px, src);
        const float by = __shfl_sync(0xffffffffu, py, src);
        const float bz = __shfl_sync(0xffffffffu, pz, src);

        if (active) {
            // Quaternion -> rotation matrix.
            const float xx = qx+qx, yy = qy+qy, zz = qz+qz;
            const float r00 = 1.f - (yy*qy + zz*qz);
            const float r11 = 1.f - (xx*qx + zz*qz);
            const float r22 = 1.f - (xx*qx + yy*qy);
            const float xy = xx*qy, xz = xx*qz, yz = yy*qz;
            const float wx = xx*qw, wy = yy*qw, wz = zz*qw;
            const float r01 = xy - wz, r10 = xy + wz;
            const float r02 = xz + wy, r20 = xz - wy;
            const float r12 = yz - wx, r21 = yz + wx;

            // A fixes joints 12..17 (cols 39..56), B fixes 18..23 (57..74).
            float* fx = swarp + (39 + half * 18) * PITCH + eW;
            #pragma unroll
            for (int k = 0; k < 6; ++k) {
                const float vx = fx[(3*k + 0) * PITCH];
                const float vy = fx[(3*k + 1) * PITCH];
                const float vz = fx[(3*k + 2) * PITCH];
                fx[(3*k + 0) * PITCH] = bx + r00*vx + r01*vy + r02*vz;
                fx[(3*k + 1) * PITCH] = by + r10*vx + r11*vy + r12*vz;
                fx[(3*k + 2) * PITCH] = bz + r20*vx + r21*vy + r22*vz;
            }
        }
    }

    __syncwarp();   // slab final

    // ---- Flush: warp-private, immediate offsets, no index math ----
    // Phase cols [off, off+NC): lane = col, iterate 16 element rows.
    {
        const int rowbase = warp * 16;
        #pragma unroll
        for (int ph = 0; ph < 3; ++ph) {
            const int off = ph * 32;
            const int NC  = (ph == 2) ? 11 : 32;
            const float* src = swarp + (off + lane) * PITCH;
            float* dst = gout + (size_t)rowbase * 75 + off + lane;
            if (full) {
                #pragma unroll
                for (int r = 0; r < 16; ++r)
                    if (lane < NC) dst[r * 75] = src[r];
            } else {
                #pragma unroll
                for (int r = 0; r < 16; ++r)
                    if (lane < NC && rowbase + r < nvalid) dst[r * 75] = src[r];
            }
        }
    }
}

extern "C" void kernel_launch(void* const* d_in, const int* in_sizes, int n_in,
                              void* d_out, int out_size) {
    const float* angles = (const float*)d_in[0];   // [B, 24]
    const float* Torg   = (const float*)d_in[1];   // [24, 4, 4]
    const float* axes   = (const float*)d_in[2];   // [24, 3]
    float* out = (float*)d_out;                    // [B, 75]

    const int B = in_sizes[0] / J;
    const int blocks = (B + EPB - 1) / EPB;
    fk_kernel<<<blocks, TPB>>>(angles, Torg, axes, out, B);
}

// round 13
// speedup vs baseline: 1.0172x; 1.0172x over previous
#include <cuda_runtime.h>

typedef unsigned long long u64;

#define J    24
#define TPB  128
#define EPB  256          // elements per block: 2 per thread, 64 per warp
#define EPU  33           // u64 per staging column (32 elem-pairs + 1 pad)

__device__ __forceinline__ u64 pk2(float lo, float hi) {
    u64 r; asm("mov.b64 %0, {%1, %2};" : "=l"(r) : "f"(lo), "f"(hi)); return r;
}
__device__ __forceinline__ void upk2(u64 v, float& lo, float& hi) {
    asm("mov.b64 {%0, %1}, %2;" : "=f"(lo), "=f"(hi) : "l"(v));
}
__device__ __forceinline__ u64 f2(u64 a, u64 b, u64 c) {   // a*b + c
    u64 d; asm("fma.rn.f32x2 %0, %1, %2, %3;" : "=l"(d) : "l"(a), "l"(b), "l"(c));
    return d;
}
__device__ __forceinline__ u64 m2(u64 a, u64 b) {          // a*b
    u64 d; asm("mul.rn.f32x2 %0, %1, %2;" : "=l"(d) : "l"(a), "l"(b));
    return d;
}
__device__ __forceinline__ u64 a2(u64 a, u64 b) {          // a+b
    u64 d; asm("add.rn.f32x2 %0, %1, %2;" : "=l"(d) : "l"(a), "l"(b));
    return d;
}

#define ONE2 0x3F8000003F800000ULL
#define TWO2 0x4000000040000000ULL
#define NEG2 0xBF800000BF800000ULL

__global__ __launch_bounds__(TPB) void fk_kernel(
    const float* __restrict__ angles,   // [B, 24]
    const float* __restrict__ Torg,     // [24, 4, 4]
    const float* __restrict__ axes,     // [24, 3] unit axes
    float* __restrict__ out,            // [B, 75]
    int B)
{
    // Per-joint consts, duplicated into both f32x2 lanes:
    // idx j*10 + {0:wx,1:wy,2:wz, 3:bx,4:by,5:bz, 6:-bx,7:-by,8:-bz, 9:pad}
    __shared__ __align__(16) float2 kjc[J * 10];
    // Warp-private phase staging: u64 slab[col][elem-pair], col pitch EPU.
    __shared__ u64 sslab[(TPB / 32)][32 * EPU];   // 33.8 KB

    const int tid  = threadIdx.x;
    const int warp = tid >> 5;
    const int lane = tid & 31;

    // ---- Warp 0: shuffle-scan of cumulative fixed rotations ----
    // C_j = Q_0 ... Q_j ;  w_j = C_j u_j ;  b_j = C_{j-1} t_j.
    if (warp == 0) {
        float m[9];
        float ax = 0.f, ay = 0.f, az = 0.f;
        float ux = 0.f, uy = 0.f, uz = 0.f;
        m[0]=1.f; m[1]=0.f; m[2]=0.f;
        m[3]=0.f; m[4]=1.f; m[5]=0.f;
        m[6]=0.f; m[7]=0.f; m[8]=1.f;
        if (lane < J) {
            const float* t = Torg + lane * 16;
            m[0]=t[0]; m[1]=t[1]; m[2]=t[2];   ax=t[3];
            m[3]=t[4]; m[4]=t[5]; m[5]=t[6];   ay=t[7];
            m[6]=t[8]; m[7]=t[9]; m[8]=t[10];  az=t[11];
            ux = axes[lane*3+0]; uy = axes[lane*3+1]; uz = axes[lane*3+2];
        }
        #pragma unroll
        for (int d = 1; d < J; d <<= 1) {          // inclusive Kogge-Stone
            float L[9];
            #pragma unroll
            for (int k = 0; k < 9; ++k)
                L[k] = __shfl_up_sync(0xffffffffu, m[k], d);
            if (lane >= d) {
                float n[9];
                #pragma unroll
                for (int r = 0; r < 3; ++r)
                    #pragma unroll
                    for (int c = 0; c < 3; ++c)
                        n[r*3+c] = L[r*3+0]*m[0*3+c] + L[r*3+1]*m[1*3+c]
                                 + L[r*3+2]*m[2*3+c];
                #pragma unroll
                for (int k = 0; k < 9; ++k) m[k] = n[k];
            }
        }
        float E[9];                                 // exclusive prefix
        #pragma unroll
        for (int k = 0; k < 9; ++k)
            E[k] = __shfl_up_sync(0xffffffffu, m[k], 1);
        if (lane == 0) {
            E[0]=1.f; E[1]=0.f; E[2]=0.f;
            E[3]=0.f; E[4]=1.f; E[5]=0.f;
            E[6]=0.f; E[7]=0.f; E[8]=1.f;
        }
        if (lane < J) {
            const float wx = m[0]*ux + m[1]*uy + m[2]*uz;   // w = C_j u
            const float wy = m[3]*ux + m[4]*uy + m[5]*uz;
            const float wz = m[6]*ux + m[7]*uy + m[8]*uz;
            const float bx = E[0]*ax + E[1]*ay + E[2]*az;   // b = C_{j-1} t
            const float by = E[3]*ax + E[4]*ay + E[5]*az;
            const float bz = E[6]*ax + E[7]*ay + E[8]*az;
            float2* o = kjc + lane * 10;
            o[0] = make_float2(wx, wx);  o[1] = make_float2(wy, wy);
            o[2] = make_float2(wz, wz);  o[3] = make_float2(bx, bx);
            o[4] = make_float2(by, by);  o[5] = make_float2(bz, bz);
            o[6] = make_float2(-bx,-bx); o[7] = make_float2(-by,-by);
            o[8] = make_float2(-bz,-bz); o[9] = make_float2(0.f, 0.f);
        }
    }

    const int base = blockIdx.x * EPB;
    const int e0 = base + warp * 64 + 2 * lane;     // this thread: e0, e0+1
    const bool v0 = (e0 < B), v1 = (e0 + 1 < B);
    const int nvalid = min(EPB, B - base);
    const bool full = (nvalid == EPB);
    float* gout = out + (size_t)base * 75;

    const float4* ap0 = reinterpret_cast<const float4*>(angles + (size_t)e0 * J);
    const float4* ap1 = ap0 + 6;   // element e0+1 (24 floats = 6 float4)

    __syncthreads();   // kjc ready

    // Packed state: quaternion P (w,x,y,z) and position p, 2 elems/lane.
    u64 Pw = ONE2, Px = 0ULL, Py = 0ULL, Pz = 0ULL;
    u64 px = 0ULL, py = 0ULL, pz = 0ULL;

    u64* slab = sslab[warp];
    const u64* C = reinterpret_cast<const u64*>(kjc);
    float A0[4], A1[4];

    // Staging: column lc, this thread's elem-pair slot.
    #define SO64(lc, v) slab[(lc) * EPU + lane] = (v)

    // Load 4 joints' angles for both elements (group g covers j=4g..4g+3).
    #define GRP(g)                                                            \
    {                                                                         \
        float4 w0_ = v0 ? __ldg(ap0 + (g)) : make_float4(0,0,0,0);            \
        float4 w1_ = v1 ? __ldg(ap1 + (g)) : make_float4(0,0,0,0);            \
        A0[0]=w0_.x; A0[1]=w0_.y; A0[2]=w0_.z; A0[3]=w0_.w;                   \
        A1[0]=w1_.x; A1[1]=w1_.y; A1[2]=w1_.z; A1[3]=w1_.w;                   \
    }

    // One packed joint step (position advance + quat update unless j==23).
    #define STEP(j)                                                           \
    {                                                                         \
        const u64 wx = C[(j)*10+0], wy = C[(j)*10+1], wz = C[(j)*10+2];       \
        const u64 bx = C[(j)*10+3], by = C[(j)*10+4], bz = C[(j)*10+5];       \
        const u64 nbx = C[(j)*10+6], nby = C[(j)*10+7], nbz = C[(j)*10+8];    \
        const u64 tx = f2(Py, bz, m2(Pz, nby));                               \
        const u64 ty = f2(Pz, bx, m2(Px, nbz));                               \
        const u64 tz = f2(Px, by, m2(Py, nbx));                               \
        const u64 ntx = m2(tx, NEG2), nty = m2(ty, NEG2), ntz = m2(tz, NEG2); \
        const u64 ox = f2(Py, tz, m2(Pz, nty));                               \
        const u64 oy = f2(Pz, tx, m2(Px, ntz));                               \
        const u64 oz = f2(Px, ty, m2(Py, ntx));                               \
        const u64 w2 = a2(Pw, Pw);                                            \
        px = a2(f2(TWO2, ox, f2(w2, tx, px)), bx);                            \
        py = a2(f2(TWO2, oy, f2(w2, ty, py)), by);                            \
        pz = a2(f2(TWO2, oz, f2(w2, tz, pz)), bz);                            \
        if ((j) < J - 1) {                                                    \
            float s0_, c0_, s1_, c1_;                                         \
            __sincosf(0.5f * A0[(j) & 3], &s0_, &c0_);                        \
            __sincosf(0.5f * A1[(j) & 3], &s1_, &c1_);                        \
            const u64 S  = pk2(s0_, s1_);                                     \
            const u64 CO = pk2(c0_, c1_);                                     \
            const u64 Sn = m2(S, NEG2);                                       \
            const u64 qx = m2(S, wx),  qy = m2(S, wy),  qz = m2(S, wz);       \
            const u64 nqx = m2(Sn, wx), nqy = m2(Sn, wy), nqz = m2(Sn, wz);   \
            const u64 nw = f2(Pz,nqz, f2(Py,nqy, f2(Px,nqx, m2(Pw,CO))));     \
            const u64 nx = f2(Pz,nqy, f2(Py,qz,  f2(Px,CO,  m2(Pw,qx))));     \
            const u64 ny = f2(Pz,qx,  f2(Py,CO,  f2(Px,nqz, m2(Pw,qy))));     \
            const u64 nz = f2(Pz,CO,  f2(Py,nqx, f2(Px,qy,  m2(Pw,qz))));     \
            Pw = nw; Px = nx; Py = ny; Pz = nz;                               \
        }                                                                     \
    }

    // Flush NC cols at output offset `off`: lane = col, iterate elem-pairs.
    // LDS.64 (banks (2*lane+2r) mod 32: conflict-free per half-warp phase),
    // STG.32 x2 coalesced across lanes.
    #define FLUSH(off, NC)                                                    \
    {                                                                         \
        __syncwarp();                                                         \
        const u64* src_ = slab + lane * EPU;                                  \
        float* dst_ = gout + (size_t)(warp * 64) * 75 + (off) + lane;         \
        if (lane < (NC)) {                                                    \
            if (full) {                                                       \
                _Pragma("unroll")                                             \
                for (int r = 0; r < 32; ++r) {                                \
                    float lo_, hi_; upk2(src_[r], lo_, hi_);                  \
                    dst_[(2*r) * 75] = lo_;                                   \
                    dst_[(2*r + 1) * 75] = hi_;                               \
                }                                                             \
            } else {                                                          \
                _Pragma("unroll")                                             \
                for (int r = 0; r < 32; ++r) {                                \
                    float lo_, hi_; upk2(src_[r], lo_, hi_);                  \
                    if (warp*64 + 2*r < nvalid)     dst_[(2*r) * 75] = lo_;   \
                    if (warp*64 + 2*r + 1 < nvalid) dst_[(2*r+1) * 75] = hi_; \
                }                                                             \
            }                                                                 \
        }                                                                     \
        __syncwarp();                                                         \
    }

    // ---- Phase 0: cols [0,32) = base(0..2) + j0..8 + j9(px,py) ----
    SO64(0, 0ULL); SO64(1, 0ULL); SO64(2, 0ULL);
    GRP(0);
    STEP(0);  SO64(3, px); SO64(4, py); SO64(5, pz);
    STEP(1);  SO64(6, px); SO64(7, py); SO64(8, pz);
    STEP(2);  SO64(9, px); SO64(10, py); SO64(11, pz);
    STEP(3);  SO64(12, px); SO64(13, py); SO64(14, pz);
    GRP(1);
    STEP(4);  SO64(15, px); SO64(16, py); SO64(17, pz);
    STEP(5);  SO64(18, px); SO64(19, py); SO64(20, pz);
    STEP(6);  SO64(21, px); SO64(22, py); SO64(23, pz);
    STEP(7);  SO64(24, px); SO64(25, py); SO64(26, pz);
    GRP(2);
    STEP(8);  SO64(27, px); SO64(28, py); SO64(29, pz);
    STEP(9);  SO64(30, px); SO64(31, py);           // pz deferred -> col 32
    FLUSH(0, 32);

    // ---- Phase 1: cols [32,64) = j9.pz + j10..19 + j20(px) ----
    SO64(0, pz);                                     // col 32
    STEP(10); SO64(1, px); SO64(2, py); SO64(3, pz);
    STEP(11); SO64(4, px); SO64(5, py); SO64(6, pz);
    GRP(3);
    STEP(12); SO64(7, px); SO64(8, py); SO64(9, pz);
    STEP(13); SO64(10, px); SO64(11, py); SO64(12, pz);
    STEP(14); SO64(13, px); SO64(14, py); SO64(15, pz);
    STEP(15); SO64(16, px); SO64(17, py); SO64(18, pz);
    GRP(4);
    STEP(16); SO64(19, px); SO64(20, py); SO64(21, pz);
    STEP(17); SO64(22, px); SO64(23, py); SO64(24, pz);
    STEP(18); SO64(25, px); SO64(26, py); SO64(27, pz);
    STEP(19); SO64(28, px); SO64(29, py); SO64(30, pz);
    GRP(5);
    STEP(20); SO64(31, px);                          // py,pz deferred -> 64,65
    FLUSH(32, 32);

    // ---- Phase 2: cols [64,75) = j20(py,pz) + j21..23 ----
    SO64(0, py); SO64(1, pz);                        // cols 64, 65
    STEP(21); SO64(2, px); SO64(3, py); SO64(4, pz);
    STEP(22); SO64(5, px); SO64(6, py); SO64(7, pz);
    STEP(23); SO64(8, px); SO64(9, py); SO64(10, pz);
    FLUSH(64, 11);

    #undef SO64
    #undef GRP
    #undef STEP
    #undef FLUSH
}

extern "C" void kernel_launch(void* const* d_in, const int* in_sizes, int n_in,
                              void* d_out, int out_size) {
    const float* angles = (const float*)d_in[0];   // [B, 24]
    const float* Torg   = (const float*)d_in[1];   // [24, 4, 4]
    const float* axes   = (const float*)d_in[2];   // [24, 3]
    float* out = (float*)d_out;                    // [B, 75]

    const int B = in_sizes[0] / J;
    const int blocks = (B + EPB - 1) / EPB;
    fk_kernel<<<blocks, TPB>>>(angles, Torg, axes, out, B);
}

// round 14
// speedup vs baseline: 1.0710x; 1.0528x over previous
#include <cuda_runtime.h>

#define J     24
#define TPB   128
#define EPB   256          // elements per block: 2 per thread, 64 per warp
#define CPIT  68           // floats per staging column (64 rows + 4 pad)
#define WSLAB (32 * CPIT)  // floats per warp slab (32 cols)

__global__ __launch_bounds__(TPB) void fk_kernel(
    const float* __restrict__ angles,   // [B, 24]
    const float* __restrict__ Torg,     // [24, 4, 4]
    const float* __restrict__ axes,     // [24, 3] unit axes
    float* __restrict__ out,            // [B, 75]
    int B)
{
    // Per-joint derived constants: {wx,wy,wz,_, bx,by,bz,_}
    __shared__ __align__(16) float kjc[J][8];
    // Warp-private col-major staging: float at col*CPIT + row,
    // row = local element (0..63). 34.8 KB total.
    __shared__ __align__(16) float sbuf[(TPB / 32) * WSLAB];

    const int tid  = threadIdx.x;
    const int warp = tid >> 5;
    const int lane = tid & 31;

    // ---- Warp 0: shuffle-scan of cumulative fixed rotations ----
    // C_j = Q_0 ... Q_j ;  w_j = C_j u_j ;  b_j = C_{j-1} t_j.
    if (warp == 0) {
        float m[9];
        float ax = 0.f, ay = 0.f, az = 0.f;
        float ux = 0.f, uy = 0.f, uz = 0.f;
        m[0]=1.f; m[1]=0.f; m[2]=0.f;
        m[3]=0.f; m[4]=1.f; m[5]=0.f;
        m[6]=0.f; m[7]=0.f; m[8]=1.f;
        if (lane < J) {
            const float* t = Torg + lane * 16;
            m[0]=t[0]; m[1]=t[1]; m[2]=t[2];   ax=t[3];
            m[3]=t[4]; m[4]=t[5]; m[5]=t[6];   ay=t[7];
            m[6]=t[8]; m[7]=t[9]; m[8]=t[10];  az=t[11];
            ux = axes[lane*3+0]; uy = axes[lane*3+1]; uz = axes[lane*3+2];
        }
        #pragma unroll
        for (int d = 1; d < J; d <<= 1) {          // inclusive Kogge-Stone
            float L[9];
            #pragma unroll
            for (int k = 0; k < 9; ++k)
                L[k] = __shfl_up_sync(0xffffffffu, m[k], d);
            if (lane >= d) {
                float n[9];
                #pragma unroll
                for (int r = 0; r < 3; ++r)
                    #pragma unroll
                    for (int c = 0; c < 3; ++c)
                        n[r*3+c] = L[r*3+0]*m[0*3+c] + L[r*3+1]*m[1*3+c]
                                 + L[r*3+2]*m[2*3+c];
                #pragma unroll
                for (int k = 0; k < 9; ++k) m[k] = n[k];
            }
        }
        float E[9];                                 // exclusive prefix
        #pragma unroll
        for (int k = 0; k < 9; ++k)
            E[k] = __shfl_up_sync(0xffffffffu, m[k], 1);
        if (lane == 0) {
            E[0]=1.f; E[1]=0.f; E[2]=0.f;
            E[3]=0.f; E[4]=1.f; E[5]=0.f;
            E[6]=0.f; E[7]=0.f; E[8]=1.f;
        }
        if (lane < J) {
            kjc[lane][0] = m[0]*ux + m[1]*uy + m[2]*uz;   // w = C_j u
            kjc[lane][1] = m[3]*ux + m[4]*uy + m[5]*uz;
            kjc[lane][2] = m[6]*ux + m[7]*uy + m[8]*uz;
            kjc[lane][3] = 0.f;
            kjc[lane][4] = E[0]*ax + E[1]*ay + E[2]*az;   // b = C_{j-1} t
            kjc[lane][5] = E[3]*ax + E[4]*ay + E[5]*az;
            kjc[lane][6] = E[6]*ax + E[7]*ay + E[8]*az;
            kjc[lane][7] = 0.f;
        }
    }

    const int base = blockIdx.x * EPB;
    const int e0 = base + warp * 64 + 2 * lane;     // this thread: e0, e0+1
    const bool v0 = (e0 < B), v1 = (e0 + 1 < B);
    const int nvalid = min(EPB, B - base);
    const bool full = (nvalid == EPB);
    float* gout = out + (size_t)base * 75;

    const float4* ap0 = reinterpret_cast<const float4*>(angles + (size_t)e0 * J);
    const float4* ap1 = ap0 + 6;   // element e0+1

    __syncthreads();   // kjc ready

    // Two independent scalar chains per thread.
    float Pw0 = 1.f, Px0 = 0.f, Py0 = 0.f, Pz0 = 0.f;
    float px0 = 0.f, py0 = 0.f, pz0 = 0.f;
    float Pw1 = 1.f, Px1 = 0.f, Py1 = 0.f, Pz1 = 0.f;
    float px1 = 0.f, py1 = 0.f, pz1 = 0.f;

    float* swarp = sbuf + warp * WSLAB;
    float2* ws = reinterpret_cast<float2*>(swarp);   // [col*34 + lane]
    const float4* kc = reinterpret_cast<const float4*>(kjc);
    float A0[4], A1[4];

    // Staged pair write: one STS.64 covers rows 2*lane, 2*lane+1 of col lc.
    #define SO(lc, a, b) ws[(lc) * (CPIT/2) + lane] = make_float2(a, b)

    // Load 4 joints' angles for both elements.
    #define GRP(g)                                                            \
    {                                                                         \
        float4 w0_ = v0 ? __ldg(ap0 + (g)) : make_float4(0,0,0,0);            \
        float4 w1_ = v1 ? __ldg(ap1 + (g)) : make_float4(0,0,0,0);            \
        A0[0]=w0_.x; A0[1]=w0_.y; A0[2]=w0_.z; A0[3]=w0_.w;                   \
        A1[0]=w1_.x; A1[1]=w1_.y; A1[2]=w1_.z; A1[3]=w1_.w;                   \
    }

    // One joint for BOTH chains (kjc loaded once, chains independent -> ILP).
    #define STEP(j)                                                           \
    {                                                                         \
        const float4 wv = kc[2*(j)];                                          \
        const float4 bv = kc[2*(j) + 1];                                      \
        /* chain 0: p += rot(P, b) */                                         \
        const float tx0 = Py0*bv.z - Pz0*bv.y;                                \
        const float ty0 = Pz0*bv.x - Px0*bv.z;                                \
        const float tz0 = Px0*bv.y - Py0*bv.x;                                \
        const float tx1 = Py1*bv.z - Pz1*bv.y;                                \
        const float ty1 = Pz1*bv.x - Px1*bv.z;                                \
        const float tz1 = Px1*bv.y - Py1*bv.x;                                \
        const float w20 = Pw0 + Pw0, w21 = Pw1 + Pw1;                         \
        const float ox0 = Py0*tz0 - Pz0*ty0;                                  \
        const float oy0 = Pz0*tx0 - Px0*tz0;                                  \
        const float oz0 = Px0*ty0 - Py0*tx0;                                  \
        const float ox1 = Py1*tz1 - Pz1*ty1;                                  \
        const float oy1 = Pz1*tx1 - Px1*tz1;                                  \
        const float oz1 = Px1*ty1 - Py1*tx1;                                  \
        px0 += bv.x + w20*tx0 + 2.f*ox0;                                      \
        py0 += bv.y + w20*ty0 + 2.f*oy0;                                      \
        pz0 += bv.z + w20*tz0 + 2.f*oz0;                                      \
        px1 += bv.x + w21*tx1 + 2.f*ox1;                                      \
        py1 += bv.y + w21*ty1 + 2.f*oy1;                                      \
        pz1 += bv.z + w21*tz1 + 2.f*oz1;                                      \
        if ((j) < J - 1) {                                                    \
            float s0_, c0_, s1_, c1_;                                         \
            __sincosf(0.5f * A0[(j) & 3], &s0_, &c0_);                        \
            __sincosf(0.5f * A1[(j) & 3], &s1_, &c1_);                        \
            const float qx0 = s0_*wv.x, qy0 = s0_*wv.y, qz0 = s0_*wv.z;       \
            const float qx1 = s1_*wv.x, qy1 = s1_*wv.y, qz1 = s1_*wv.z;       \
            const float nw0 = Pw0*c0_ - Px0*qx0 - Py0*qy0 - Pz0*qz0;          \
            const float nx0 = Pw0*qx0 + Px0*c0_ + Py0*qz0 - Pz0*qy0;          \
            const float ny0 = Pw0*qy0 - Px0*qz0 + Py0*c0_ + Pz0*qx0;          \
            const float nz0 = Pw0*qz0 + Px0*qy0 - Py0*qx0 + Pz0*c0_;          \
            const float nw1 = Pw1*c1_ - Px1*qx1 - Py1*qy1 - Pz1*qz1;          \
            const float nx1 = Pw1*qx1 + Px1*c1_ + Py1*qz1 - Pz1*qy1;          \
            const float ny1 = Pw1*qy1 - Px1*qz1 + Py1*c1_ + Pz1*qx1;          \
            const float nz1 = Pw1*qz1 + Px1*qy1 - Py1*qx1 + Pz1*c1_;          \
            Pw0 = nw0; Px0 = nx0; Py0 = ny0; Pz0 = nz0;                       \
            Pw1 = nw1; Px1 = nx1; Py1 = ny1; Pz1 = nz1;                       \
        }                                                                     \
    }

    // Flush NC cols at output offset `off`: lane = col, LDS.128 reads 4 rows
    // (pitch 68 -> 4*lane mod 32 distinct per 8-lane phase: conflict-free),
    // then 4 coalesced STG.32.
    #define FLUSH(off, NC)                                                    \
    {                                                                         \
        __syncwarp();                                                         \
        if (lane < (NC)) {                                                    \
            const float4* fs =                                                \
                reinterpret_cast<const float4*>(swarp + lane * CPIT);         \
            float* dst_ = gout + (size_t)(warp * 64) * 75 + (off) + lane;     \
            if (full) {                                                       \
                _Pragma("unroll")                                             \
                for (int r = 0; r < 16; ++r) {                                \
                    const float4 v_ = fs[r];                                  \
                    dst_[(4*r + 0) * 75] = v_.x;                              \
                    dst_[(4*r + 1) * 75] = v_.y;                              \
                    dst_[(4*r + 2) * 75] = v_.z;                              \
                    dst_[(4*r + 3) * 75] = v_.w;                              \
                }                                                             \
            } else {                                                          \
                _Pragma("unroll")                                             \
                for (int r = 0; r < 16; ++r) {                                \
                    const float4 v_ = fs[r];                                  \
                    const int rb_ = warp * 64 + 4*r;                          \
                    if (rb_ + 0 < nvalid) dst_[(4*r + 0) * 75] = v_.x;        \
                    if (rb_ + 1 < nvalid) dst_[(4*r + 1) * 75] = v_.y;        \
                    if (rb_ + 2 < nvalid) dst_[(4*r + 2) * 75] = v_.z;        \
                    if (rb_ + 3 < nvalid) dst_[(4*r + 3) * 75] = v_.w;        \
                }                                                             \
            }                                                                 \
        }                                                                     \
        __syncwarp();                                                         \
    }

    // ---- Phase 0: cols [0,32) = base(0..2) + j0..8 + j9(px,py) ----
    SO(0, 0.f, 0.f); SO(1, 0.f, 0.f); SO(2, 0.f, 0.f);
    GRP(0);
    STEP(0);  SO(3, px0, px1);  SO(4, py0, py1);  SO(5, pz0, pz1);
    STEP(1);  SO(6, px0, px1);  SO(7, py0, py1);  SO(8, pz0, pz1);
    STEP(2);  SO(9, px0, px1);  SO(10, py0, py1); SO(11, pz0, pz1);
    STEP(3);  SO(12, px0, px1); SO(13, py0, py1); SO(14, pz0, pz1);
    GRP(1);
    STEP(4);  SO(15, px0, px1); SO(16, py0, py1); SO(17, pz0, pz1);
    STEP(5);  SO(18, px0, px1); SO(19, py0, py1); SO(20, pz0, pz1);
    STEP(6);  SO(21, px0, px1); SO(22, py0, py1); SO(23, pz0, pz1);
    STEP(7);  SO(24, px0, px1); SO(25, py0, py1); SO(26, pz0, pz1);
    GRP(2);
    STEP(8);  SO(27, px0, px1); SO(28, py0, py1); SO(29, pz0, pz1);
    STEP(9);  SO(30, px0, px1); SO(31, py0, py1);   // pz -> col 32 (deferred)
    FLUSH(0, 32);

    // ---- Phase 1: cols [32,64) = j9.pz + j10..19 + j20(px) ----
    SO(0, pz0, pz1);                                 // col 32
    STEP(10); SO(1, px0, px1);  SO(2, py0, py1);  SO(3, pz0, pz1);
    STEP(11); SO(4, px0, px1);  SO(5, py0, py1);  SO(6, pz0, pz1);
    GRP(3);
    STEP(12); SO(7, px0, px1);  SO(8, py0, py1);  SO(9, pz0, pz1);
    STEP(13); SO(10, px0, px1); SO(11, py0, py1); SO(12, pz0, pz1);
    STEP(14); SO(13, px0, px1); SO(14, py0, py1); SO(15, pz0, pz1);
    STEP(15); SO(16, px0, px1); SO(17, py0, py1); SO(18, pz0, pz1);
    GRP(4);
    STEP(16); SO(19, px0, px1); SO(20, py0, py1); SO(21, pz0, pz1);
    STEP(17); SO(22, px0, px1); SO(23, py0, py1); SO(24, pz0, pz1);
    STEP(18); SO(25, px0, px1); SO(26, py0, py1); SO(27, pz0, pz1);
    STEP(19); SO(28, px0, px1); SO(29, py0, py1); SO(30, pz0, pz1);
    GRP(5);
    STEP(20); SO(31, px0, px1);                      // py,pz -> cols 64,65
    FLUSH(32, 32);

    // ---- Phase 2: cols [64,75) = j20(py,pz) + j21..23 ----
    SO(0, py0, py1); SO(1, pz0, pz1);                // cols 64, 65
    STEP(21); SO(2, px0, px1); SO(3, py0, py1); SO(4, pz0, pz1);
    STEP(22); SO(5, px0, px1); SO(6, py0, py1); SO(7, pz0, pz1);
    STEP(23); SO(8, px0, px1); SO(9, py0, py1); SO(10, pz0, pz1);
    FLUSH(64, 11);

    #undef SO
    #undef GRP
    #undef STEP
    #undef FLUSH
}

extern "C" void kernel_launch(void* const* d_in, const int* in_sizes, int n_in,
                              void* d_out, int out_size) {
    const float* angles = (const float*)d_in[0];   // [B, 24]
    const float* Torg   = (const float*)d_in[1];   // [24, 4, 4]
    const float* axes   = (const float*)d_in[2];   // [24, 3]
    float* out = (float*)d_out;                    // [B, 75]

    const int B = in_sizes[0] / J;
    const int blocks = (B + EPB - 1) / EPB;
    fk_kernel<<<blocks, TPB>>>(angles, Torg, axes, out, B);
}

// round 15
// speedup vs baseline: 1.1228x; 1.0484x over previous
#include <cuda_runtime.h>

#define J    24
#define TPB  128

__global__ __launch_bounds__(TPB) void fk_kernel(
    const float* __restrict__ angles,   // [B, 24]
    const float* __restrict__ Torg,     // [24, 4, 4]
    const float* __restrict__ axes,     // [24, 3] unit axes
    float* __restrict__ out,            // [B, 75]
    int B)
{
    // Per-joint derived constants: {wx,wy,wz,_, bx,by,bz,_}
    __shared__ __align__(16) float kjc[J][8];
    // Full output staging: thread t owns s_out[t*75 .. t*75+74].
    // Pitch 75 odd -> conflict-free; flushed once with float4.
    __shared__ __align__(16) float s_out[TPB * 75];

    const int tid  = threadIdx.x;
    const int warp = tid >> 5;
    const int lane = tid & 31;

    // ---- Warp 0: shuffle-scan of cumulative fixed rotations ----
    // C_j = Q_0 ... Q_j ;  w_j = C_j u_j ;  b_j = C_{j-1} t_j.
    if (warp == 0) {
        float m[9];
        float ax = 0.f, ay = 0.f, az = 0.f;
        float ux = 0.f, uy = 0.f, uz = 0.f;
        m[0]=1.f; m[1]=0.f; m[2]=0.f;
        m[3]=0.f; m[4]=1.f; m[5]=0.f;
        m[6]=0.f; m[7]=0.f; m[8]=1.f;
        if (lane < J) {
            const float* t = Torg + lane * 16;
            m[0]=t[0]; m[1]=t[1]; m[2]=t[2];   ax=t[3];
            m[3]=t[4]; m[4]=t[5]; m[5]=t[6];   ay=t[7];
            m[6]=t[8]; m[7]=t[9]; m[8]=t[10];  az=t[11];
            ux = axes[lane*3+0]; uy = axes[lane*3+1]; uz = axes[lane*3+2];
        }
        #pragma unroll
        for (int d = 1; d < J; d <<= 1) {          // inclusive Kogge-Stone
            float L[9];
            #pragma unroll
            for (int k = 0; k < 9; ++k)
                L[k] = __shfl_up_sync(0xffffffffu, m[k], d);
            if (lane >= d) {
                float n[9];
                #pragma unroll
                for (int r = 0; r < 3; ++r)
                    #pragma unroll
                    for (int c = 0; c < 3; ++c)
                        n[r*3+c] = L[r*3+0]*m[0*3+c] + L[r*3+1]*m[1*3+c]
                                 + L[r*3+2]*m[2*3+c];
                #pragma unroll
                for (int k = 0; k < 9; ++k) m[k] = n[k];
            }
        }
        float E[9];                                 // exclusive prefix
        #pragma unroll
        for (int k = 0; k < 9; ++k)
            E[k] = __shfl_up_sync(0xffffffffu, m[k], 1);
        if (lane == 0) {
            E[0]=1.f; E[1]=0.f; E[2]=0.f;
            E[3]=0.f; E[4]=1.f; E[5]=0.f;
            E[6]=0.f; E[7]=0.f; E[8]=1.f;
        }
        if (lane < J) {
            kjc[lane][0] = m[0]*ux + m[1]*uy + m[2]*uz;   // w = C_j u
            kjc[lane][1] = m[3]*ux + m[4]*uy + m[5]*uz;
            kjc[lane][2] = m[6]*ux + m[7]*uy + m[8]*uz;
            kjc[lane][3] = 0.f;
            kjc[lane][4] = E[0]*ax + E[1]*ay + E[2]*az;   // b = C_{j-1} t
            kjc[lane][5] = E[3]*ax + E[4]*ay + E[5]*az;
            kjc[lane][6] = E[6]*ax + E[7]*ay + E[8]*az;
            kjc[lane][7] = 0.f;
        }
    }

    const int base = blockIdx.x * TPB;
    const int e = base + tid;
    const bool active = (e < B);

    // All 24 angles: 6 LDG.128 (row start e*96 B is 16B aligned).
    float a[J];
    if (active) {
        const float4* ap = reinterpret_cast<const float4*>(angles + (size_t)e * J);
        #pragma unroll
        for (int q = 0; q < J / 4; ++q) {
            float4 v = __ldg(ap + q);
            a[4*q+0] = v.x; a[4*q+1] = v.y; a[4*q+2] = v.z; a[4*q+3] = v.w;
        }
    }

    __syncthreads();   // kjc ready

    if (active) {
        // Chain A (joints 0..11, absolute) and chain B (joints 12..23 from
        // identity, relative) — two independent dependency chains per thread.
        float Pw = 1.f, Px = 0.f, Py = 0.f, Pz = 0.f;   // A quat
        float px = 0.f, py = 0.f, pz = 0.f;             // A pos
        float Qw = 1.f, Qx = 0.f, Qy = 0.f, Qz = 0.f;   // B quat
        float qx = 0.f, qy = 0.f, qz = 0.f;             // B pos (relative)

        float* so = s_out + tid * 75;
        so[0] = 0.f; so[1] = 0.f; so[2] = 0.f;   // base_pos

        const float4* kc = reinterpret_cast<const float4*>(kjc);

        // One joint step on a named state. doquat: advance the quaternion.
        #define STEP(j, doquat, PW,PX,PY,PZ, SX,SY,SZ)                        \
        {                                                                     \
            const float4 wv = kc[2*(j)];                                      \
            const float4 bv = kc[2*(j) + 1];                                  \
            const float tx = PY*bv.z - PZ*bv.y;                               \
            const float ty = PZ*bv.x - PX*bv.z;                               \
            const float tz = PX*bv.y - PY*bv.x;                               \
            const float w2 = PW + PW;                                         \
            const float ox = PY*tz - PZ*ty;                                   \
            const float oy = PZ*tx - PX*tz;                                   \
            const float oz = PX*ty - PY*tx;                                   \
            SX += bv.x + w2*tx + 2.f*ox;                                      \
            SY += bv.y + w2*ty + 2.f*oy;                                      \
            SZ += bv.z + w2*tz + 2.f*oz;                                      \
            if (doquat) {                                                     \
                float s_, c_;                                                 \
                __sincosf(0.5f * a[(j)], &s_, &c_);                           \
                const float gx = s_*wv.x, gy = s_*wv.y, gz = s_*wv.z;         \
                const float nw = PW*c_ - PX*gx - PY*gy - PZ*gz;               \
                const float nx = PW*gx + PX*c_ + PY*gz - PZ*gy;               \
                const float ny = PW*gy - PX*gz + PY*c_ + PZ*gx;               \
                const float nz = PW*gz + PX*gy - PY*gx + PZ*c_;               \
                PW = nw; PX = nx; PY = ny; PZ = nz;                           \
            }                                                                 \
        }

        #pragma unroll
        for (int k = 0; k < 12; ++k) {
            // Chain A: joint k (quat needed through j=11 for the fixup).
            STEP(k, true, Pw,Px,Py,Pz, px,py,pz);
            so[3 + 3*k + 0] = px;
            so[3 + 3*k + 1] = py;
            so[3 + 3*k + 2] = pz;
            // Chain B: joint 12+k (relative; quat not needed after j=22).
            STEP(12 + k, (k < 11), Qw,Qx,Qy,Qz, qx,qy,qz);
            so[39 + 3*k + 0] = qx;
            so[39 + 3*k + 1] = qy;
            so[39 + 3*k + 2] = qz;
        }
        #undef STEP

        // ---- Fixup: p_j = p11 + R(P11) * p'_j for joints 12..23 ----
        // R from unit quaternion P11.
        const float xx = Px+Px, yy = Py+Py, zz = Pz+Pz;
        const float r00 = 1.f - (yy*Py + zz*Pz);
        const float r11 = 1.f - (xx*Px + zz*Pz);
        const float r22 = 1.f - (xx*Px + yy*Py);
        const float xy = xx*Py, xz = xx*Pz, yz = yy*Pz;
        const float wx = xx*Pw, wy = yy*Pw, wz = zz*Pw;
        const float r01 = xy - wz, r10 = xy + wz;
        const float r02 = xz + wy, r20 = xz - wy;
        const float r12 = yz - wx, r21 = yz + wx;

        #pragma unroll
        for (int k = 0; k < 12; ++k) {
            const float vx = so[39 + 3*k + 0];
            const float vy = so[39 + 3*k + 1];
            const float vz = so[39 + 3*k + 2];
            so[39 + 3*k + 0] = px + r00*vx + r01*vy + r02*vz;
            so[39 + 3*k + 1] = py + r10*vx + r11*vy + r12*vz;
            so[39 + 3*k + 2] = pz + r20*vx + r21*vy + r22*vz;
        }
    }

    __syncthreads();   // s_out fully staged

    // Single fully-coalesced float4 flush of the [TPB, 75] slab.
    const int nvalid = min(TPB, B - base);
    float* gout = out + (size_t)base * 75;
    if (nvalid == TPB) {
        const float4* sv = reinterpret_cast<const float4*>(s_out);
        float4* gv = reinterpret_cast<float4*>(gout);
        #pragma unroll 5
        for (int i = tid; i < TPB * 75 / 4; i += TPB) gv[i] = sv[i];
    } else if (nvalid > 0) {
        const int cnt = nvalid * 75;
        for (int i = tid; i < cnt; i += TPB) gout[i] = s_out[i];
    }
}

extern "C" void kernel_launch(void* const* d_in, const int* in_sizes, int n_in,
                              void* d_out, int out_size) {
    const float* angles = (const float*)d_in[0];   // [B, 24]
    const float* Torg   = (const float*)d_in[1];   // [24, 4, 4]
    const float* axes   = (const float*)d_in[2];   // [24, 3]
    float* out = (float*)d_out;                    // [B, 75]

    const int B = in_sizes[0] / J;
    const int blocks = (B + TPB - 1) / TPB;
    fk_kernel<<<blocks, TPB>>>(angles, Torg, axes, out, B);
}

// round 16
// speedup vs baseline: 1.1366x; 1.0123x over previous
#include <cuda_runtime.h>

#define J    24
#define TPB  128

__global__ __launch_bounds__(TPB) void fk_kernel(
    const float* __restrict__ angles,   // [B, 24]
    const float* __restrict__ Torg,     // [24, 4, 4]
    const float* __restrict__ axes,     // [24, 3] unit axes
    float* __restrict__ out,            // [B, 75]
    int B)
{
    // Per-joint derived constants: {wx,wy,wz,_, bx,by,bz,_}
    __shared__ __align__(16) float kjc[J][8];
    // Row-major staging: thread t owns s_out[t*75 .. t*75+74].
    // Pitch 75 (odd) -> compute-side STS conflict-free; flush is linear.
    __shared__ __align__(16) float s_out[TPB * 75];

    const int tid  = threadIdx.x;
    const int warp = tid >> 5;
    const int lane = tid & 31;

    // ---- Warp 0: shuffle-scan of cumulative fixed rotations ----
    // C_j = Q_0 ... Q_j ;  w_j = C_j u_j ;  b_j = C_{j-1} t_j.
    if (warp == 0) {
        float m[9];
        float ax = 0.f, ay = 0.f, az = 0.f;
        float ux = 0.f, uy = 0.f, uz = 0.f;
        m[0]=1.f; m[1]=0.f; m[2]=0.f;
        m[3]=0.f; m[4]=1.f; m[5]=0.f;
        m[6]=0.f; m[7]=0.f; m[8]=1.f;
        if (lane < J) {
            const float* t = Torg + lane * 16;
            m[0]=t[0]; m[1]=t[1]; m[2]=t[2];   ax=t[3];
            m[3]=t[4]; m[4]=t[5]; m[5]=t[6];   ay=t[7];
            m[6]=t[8]; m[7]=t[9]; m[8]=t[10];  az=t[11];
            ux = axes[lane*3+0]; uy = axes[lane*3+1]; uz = axes[lane*3+2];
        }
        #pragma unroll
        for (int d = 1; d < J; d <<= 1) {          // inclusive Kogge-Stone
            float L[9];
            #pragma unroll
            for (int k = 0; k < 9; ++k)
                L[k] = __shfl_up_sync(0xffffffffu, m[k], d);
            if (lane >= d) {
                float n[9];
                #pragma unroll
                for (int r = 0; r < 3; ++r)
                    #pragma unroll
                    for (int c = 0; c < 3; ++c)
                        n[r*3+c] = L[r*3+0]*m[0*3+c] + L[r*3+1]*m[1*3+c]
                                 + L[r*3+2]*m[2*3+c];
                #pragma unroll
                for (int k = 0; k < 9; ++k) m[k] = n[k];
            }
        }
        float E[9];                                 // exclusive prefix
        #pragma unroll
        for (int k = 0; k < 9; ++k)
            E[k] = __shfl_up_sync(0xffffffffu, m[k], 1);
        if (lane == 0) {
            E[0]=1.f; E[1]=0.f; E[2]=0.f;
            E[3]=0.f; E[4]=1.f; E[5]=0.f;
            E[6]=0.f; E[7]=0.f; E[8]=1.f;
        }
        if (lane < J) {
            kjc[lane][0] = m[0]*ux + m[1]*uy + m[2]*uz;   // w = C_j u
            kjc[lane][1] = m[3]*ux + m[4]*uy + m[5]*uz;
            kjc[lane][2] = m[6]*ux + m[7]*uy + m[8]*uz;
            kjc[lane][3] = 0.f;
            kjc[lane][4] = E[0]*ax + E[1]*ay + E[2]*az;   // b = C_{j-1} t
            kjc[lane][5] = E[3]*ax + E[4]*ay + E[5]*az;
            kjc[lane][6] = E[6]*ax + E[7]*ay + E[8]*az;
            kjc[lane][7] = 0.f;
        }
    }

    const int base = blockIdx.x * TPB;
    const bool full = (base + TPB <= B);
    const int e = base + tid;
    const bool active = full || (e < B);

    // All 24 angles: 6 LDG.128 (row start e*96 B is 16B aligned).
    float a[J];
    if (active) {
        const float4* ap = reinterpret_cast<const float4*>(angles + (size_t)e * J);
        #pragma unroll
        for (int q = 0; q < J / 4; ++q) {
            float4 v = __ldg(ap + q);
            a[4*q+0] = v.x; a[4*q+1] = v.y; a[4*q+2] = v.z; a[4*q+3] = v.w;
        }
    }

    __syncthreads();   // kjc ready (only block-wide barrier)

    if (active) {
        // State: quaternion P (w,x,y,z) and position p.
        float Pw = 1.f, Px = 0.f, Py = 0.f, Pz = 0.f;
        float px = 0.f, py = 0.f, pz = 0.f;

        float* so = s_out + tid * 75;
        so[0] = 0.f; so[1] = 0.f; so[2] = 0.f;   // base_pos

        const float4* kc = reinterpret_cast<const float4*>(kjc);

        #pragma unroll
        for (int j = 0; j < J; ++j) {
            const float4 wv = kc[2*j];       // w_j (broadcast LDS)
            const float4 bv = kc[2*j + 1];   // b_j

            // p += rot(P, b):  t = qv x b;  p += b + 2*Pw*t + 2*(qv x t)
            const float tx = Py*bv.z - Pz*bv.y;
            const float ty = Pz*bv.x - Px*bv.z;
            const float tz = Px*bv.y - Py*bv.x;
            const float w2 = Pw + Pw;
            const float ox = Py*tz - Pz*ty;
            const float oy = Pz*tx - Px*tz;
            const float oz = Px*ty - Py*tx;
            px += bv.x + w2*tx + 2.f*ox;
            py += bv.y + w2*ty + 2.f*oy;
            pz += bv.z + w2*tz + 2.f*oz;

            so[3 + 3*j + 0] = px;
            so[3 + 3*j + 1] = py;
            so[3 + 3*j + 2] = pz;

            // P <- P (x) (cos h, sin h * w)   [skip after last joint]
            if (j < J - 1) {
                float s, co;
                __sincosf(0.5f * a[j], &s, &co);
                const float qx = s*wv.x, qy = s*wv.y, qz = s*wv.z;
                const float nw = Pw*co - Px*qx - Py*qy - Pz*qz;
                const float nx = Pw*qx + Px*co + Py*qz - Pz*qy;
                const float ny = Pw*qy - Px*qz + Py*co + Pz*qx;
                const float nz = Pw*qz + Px*qy - Py*qx + Pz*co;
                Pw = nw; Px = nx; Py = ny; Pz = nz;
            }
        }
    }

    // ---- Warp-private flush: each warp moves its own 32x75 slab ----
    // 600 float4 per warp, linear (conflict-free LDS.128, coalesced STG.128).
    __syncwarp();
    {
        const float4* sv =
            reinterpret_cast<const float4*>(s_out + warp * 32 * 75);
        float* gbase = out + (size_t)base * 75 + warp * 32 * 75;
        if (full) {
            float4* gv = reinterpret_cast<float4*>(gbase);
            #pragma unroll
            for (int k = 0; k < 18; ++k)          // 18*32 = 576
                gv[32*k + lane] = sv[32*k + lane];
            if (lane < 24)                         // remaining 24
                gv[576 + lane] = sv[576 + lane];
        } else {
            // Generic tail path (unused for B % 128 == 0).
            const int nvalid = min(TPB, B - base) - warp * 32;
            if (nvalid > 0) {
                const int cnt = min(nvalid, 32) * 75;
                const float* sf = s_out + warp * 32 * 75;
                for (int i = lane; i < cnt; i += 32) gbase[i] = sf[i];
            }
        }
    }
}

extern "C" void kernel_launch(void* const* d_in, const int* in_sizes, int n_in,
                              void* d_out, int out_size) {
    const float* angles = (const float*)d_in[0];   // [B, 24]
    const float* Torg   = (const float*)d_in[1];   // [24, 4, 4]
    const float* axes   = (const float*)d_in[2];   // [24, 3]
    float* out = (float*)d_out;                    // [B, 75]

    const int B = in_sizes[0] / J;
    const int blocks = (B + TPB - 1) / TPB;
    fk_kernel<<<blocks, TPB>>>(angles, Torg, axes, out, B);
}